// round 3
// baseline (speedup 1.0000x reference)
#include <cuda_runtime.h>
#include <math_constants.h>

// ---------------- problem constants ----------------
#define BB 2
#define NV 6
#define DIMC 128
#define QCNT 2304   // 48*48
#define KCNT 576    // 24*24
#define HEADS 4
#define DH 32
#define BH (BB*HEADS)          // 8
#define NSPLIT 2
#define KSPL (KCNT/NSPLIT)     // 288
#define NPART (NV*NSPLIT)      // 12
#define SCALEF 0.17677669529663689f  // 32^-0.5

typedef unsigned long long u64;

// ---------------- f32x2 packed helpers ----------------
__device__ __forceinline__ u64 f2_fma(u64 a, u64 b, u64 c) {
    u64 d; asm("fma.rn.f32x2 %0,%1,%2,%3;" : "=l"(d) : "l"(a), "l"(b), "l"(c)); return d;
}
__device__ __forceinline__ u64 f2_mul(u64 a, u64 b) {
    u64 d; asm("mul.rn.f32x2 %0,%1,%2;" : "=l"(d) : "l"(a), "l"(b)); return d;
}
__device__ __forceinline__ u64 f2_add(u64 a, u64 b) {
    u64 d; asm("add.rn.f32x2 %0,%1,%2;" : "=l"(d) : "l"(a), "l"(b)); return d;
}
__device__ __forceinline__ u64 f2_pack(float lo, float hi) {
    u64 d; asm("mov.b64 %0,{%1,%2};" : "=l"(d) : "r"(__float_as_uint(lo)), "r"(__float_as_uint(hi))); return d;
}
__device__ __forceinline__ u64 f2_dup(float x) {
    u64 d; asm("mov.b64 %0,{%1,%1};" : "=l"(d) : "r"(__float_as_uint(x))); return d;
}
__device__ __forceinline__ void f2_unpack(float& lo, float& hi, u64 v) {
    unsigned a, b; asm("mov.b64 {%0,%1},%2;" : "=r"(a), "=r"(b) : "l"(v));
    lo = __uint_as_float(a); hi = __uint_as_float(b);
}

// ---------------- scratch (device globals; no allocation allowed) ----------------
__device__ float g_qp[BH * NV * QCNT * DH];
__device__ float g_kp[BH * NV * KCNT * DH];
__device__ float g_vp[BH * NV * KCNT * DH];
__device__ float g_Opart[BH * NPART * QCNT * DH];   // 7,077,888
__device__ float g_ml[BH * NPART * QCNT * 2];

// ==================================================================
// Kernel 1: LN + projection for q,k,v in ONE launch.
// q: blocks [0,216)   128-row tiles (8 rows/thread)
// k: blocks [216,324) 64-row tiles  (4 rows/thread)
// v: blocks [324,432) 64-row tiles
// 256 threads; dynamic smem: As[ROWS*129] (<=66048B)
// ==================================================================
#define PJS 129

template<int RPT>
__device__ __forceinline__ void proj_gemm(
    const float* __restrict__ As, const float* __restrict__ Wt,
    const float* __restrict__ biasv, float* __restrict__ outp,
    int b, int n, int S, int s0, int tid)
{
    int rg = tid >> 4;
    int c0 = (tid & 15) * 8;
    u64 acc[RPT][4];
    #pragma unroll
    for (int i = 0; i < RPT; i++)
        #pragma unroll
        for (int j = 0; j < 4; j++) acc[i][j] = 0ull;

    #pragma unroll 2
    for (int k = 0; k < 128; k++) {
        const double* Wd = (const double*)(Wt + k * 128 + c0);
        u64 w0 = __double_as_longlong(Wd[0]);
        u64 w1 = __double_as_longlong(Wd[1]);
        u64 w2 = __double_as_longlong(Wd[2]);
        u64 w3 = __double_as_longlong(Wd[3]);
        #pragma unroll
        for (int i = 0; i < RPT; i++) {
            u64 av = f2_dup(As[(RPT * rg + i) * PJS + k]);
            acc[i][0] = f2_fma(av, w0, acc[i][0]);
            acc[i][1] = f2_fma(av, w1, acc[i][1]);
            acc[i][2] = f2_fma(av, w2, acc[i][2]);
            acc[i][3] = f2_fma(av, w3, acc[i][3]);
        }
    }
    const double* Bd = (const double*)(biasv + c0);
    u64 bb0 = __double_as_longlong(Bd[0]);
    u64 bb1 = __double_as_longlong(Bd[1]);
    u64 bb2 = __double_as_longlong(Bd[2]);
    u64 bb3 = __double_as_longlong(Bd[3]);
    int head = c0 >> 5, dh0 = c0 & 31;
    #pragma unroll
    for (int i = 0; i < RPT; i++) {
        int qrow = s0 + RPT * rg + i;
        u64* dst = (u64*)(outp + ((((size_t)(b * HEADS + head) * NV + n) * S + qrow) * DH + dh0));
        dst[0] = f2_add(acc[i][0], bb0);
        dst[1] = f2_add(acc[i][1], bb1);
        dst[2] = f2_add(acc[i][2], bb2);
        dst[3] = f2_add(acc[i][3], bb3);
    }
}

__global__ __launch_bounds__(256) void proj_all_kernel(
    const float* __restrict__ qi, const float* __restrict__ ki, const float* __restrict__ vi,
    const float* __restrict__ lnqg, const float* __restrict__ lnqb,
    const float* __restrict__ Wq, const float* __restrict__ bq,
    const float* __restrict__ lnkg, const float* __restrict__ lnkb,
    const float* __restrict__ Wk, const float* __restrict__ bk,
    const float* __restrict__ lnvg, const float* __restrict__ lnvb,
    const float* __restrict__ Wv, const float* __restrict__ bv,
    float* __restrict__ qo, float* __restrict__ ko, float* __restrict__ vo)
{
    extern __shared__ float As[];       // [ROWS * PJS]
    __shared__ float s_mean[128], s_rstd[128];
    int blk = blockIdx.x;
    int tid = threadIdx.x;

    const float* X; const float* lng; const float* lnb;
    const float* Wt; const float* biasv; float* outp; int S, local, ROWS;
    if (blk < 216)      { X = qi; lng = lnqg; lnb = lnqb; Wt = Wq; biasv = bq; outp = qo; S = QCNT; local = blk;       ROWS = 128; }
    else if (blk < 324) { X = ki; lng = lnkg; lnb = lnkb; Wt = Wk; biasv = bk; outp = ko; S = KCNT; local = blk - 216; ROWS = 64; }
    else                { X = vi; lng = lnvg; lnb = lnvb; Wt = Wv; biasv = bv; outp = vo; S = KCNT; local = blk - 324; ROWS = 64; }

    int tiles = S / ROWS;
    int t = local % tiles;
    int bn = local / tiles;            // b*6+n
    int b = bn / NV, n = bn % NV;
    int s0 = t * ROWS;
    const float* Xb = X + (size_t)bn * DIMC * S;

    int total = ROWS * 128;
    // coalesced load: consecutive tid -> consecutive spatial row (per channel)
    for (int idx = tid; idx < total; idx += 256) {
        int c = idx / ROWS, r = idx - c * ROWS;
        As[r * PJS + c] = Xb[(size_t)c * S + s0 + r];
    }
    __syncthreads();
    if (tid < ROWS) {
        float s = 0.f, s2 = 0.f;
        const float* row = &As[tid * PJS];
        #pragma unroll 8
        for (int c = 0; c < 128; c++) { float x = row[c]; s += x; s2 += x * x; }
        float mn = s * (1.f / 128.f);
        float vv = s2 * (1.f / 128.f) - mn * mn;
        s_mean[tid] = mn; s_rstd[tid] = rsqrtf(vv + 1e-5f);
    }
    __syncthreads();
    for (int idx = tid; idx < total; idx += 256) {
        int r = idx >> 7, c = idx & 127;
        As[r * PJS + c] = (As[r * PJS + c] - s_mean[r]) * s_rstd[r] * lng[c] + lnb[c];
    }
    __syncthreads();

    if (ROWS == 128) proj_gemm<8>(As, Wt, biasv, outp, b, n, S, s0, tid);
    else             proj_gemm<4>(As, Wt, biasv, outp, b, n, S, s0, tid);
}

// ==================================================================
// Kernel 2: per-(view,split) flash attention partials. 2 queries/thread.
// grid (18, 12, 8), 64 threads. Each block: 288 keys in 3x96 chunks.
// ==================================================================
__global__ __launch_bounds__(64) void attn_kernel(
    const float* __restrict__ qp, const float* __restrict__ kp,
    const float* __restrict__ vp, float* __restrict__ Opart,
    float* __restrict__ ml)
{
    __shared__ float4 Ksm[768];
    __shared__ float4 Vsm[768];
    int qt = blockIdx.x;
    int ns = blockIdx.y;                 // n*2 + split
    int bh = blockIdx.z;
    int n = ns >> 1, split = ns & 1;
    int tid = threadIdx.x;
    size_t view = (size_t)bh * NV + n;
    size_t view2 = view * NSPLIT + split;
    int base = split * KSPL;

    u64 qu[2][16];
    #pragma unroll
    for (int s = 0; s < 2; s++) {
        const float* qrow = qp + (view * QCNT + qt * 128 + s * 64 + tid) * DH;
        #pragma unroll
        for (int e = 0; e < 16; e++)
            qu[s][e] = f2_pack(qrow[2 * e] * SCALEF, qrow[2 * e + 1] * SCALEF);
    }
    u64 Ov[2][16];
    #pragma unroll
    for (int s = 0; s < 2; s++)
        #pragma unroll
        for (int e = 0; e < 16; e++) Ov[s][e] = 0ull;
    float m0 = -CUDART_INF_F, m1 = -CUDART_INF_F, l0 = 0.f, l1 = 0.f;

    const float4* Kb = (const float4*)(kp + view * KCNT * DH);
    const float4* Vb = (const float4*)(vp + view * KCNT * DH);

    for (int cc = 0; cc < 3; cc++) {
        int c0 = base + cc * 96;
        __syncthreads();
        #pragma unroll
        for (int i = 0; i < 12; i++) {
            int f = i * 64 + tid;
            Ksm[f] = Kb[c0 * 8 + f];
            Vsm[f] = Vb[c0 * 8 + f];
        }
        __syncthreads();
        #pragma unroll 1
        for (int g = 0; g < 12; g++) {
            float sc0[8], sc1[8];
            #pragma unroll
            for (int j = 0; j < 8; j++) {
                const double2* Kr = (const double2*)&Ksm[(g * 8 + j) * 8];
                u64 a00 = 0, a01 = 0, a10 = 0, a11 = 0;
                #pragma unroll
                for (int i = 0; i < 4; i++) {
                    double2 d0 = Kr[2 * i];
                    double2 d1 = Kr[2 * i + 1];
                    u64 k0 = __double_as_longlong(d0.x), k1 = __double_as_longlong(d0.y);
                    u64 k2 = __double_as_longlong(d1.x), k3 = __double_as_longlong(d1.y);
                    a00 = f2_fma(qu[0][4 * i + 0], k0, a00);
                    a01 = f2_fma(qu[0][4 * i + 1], k1, a01);
                    a00 = f2_fma(qu[0][4 * i + 2], k2, a00);
                    a01 = f2_fma(qu[0][4 * i + 3], k3, a01);
                    a10 = f2_fma(qu[1][4 * i + 0], k0, a10);
                    a11 = f2_fma(qu[1][4 * i + 1], k1, a11);
                    a10 = f2_fma(qu[1][4 * i + 2], k2, a10);
                    a11 = f2_fma(qu[1][4 * i + 3], k3, a11);
                }
                float lo, hi;
                f2_unpack(lo, hi, f2_add(a00, a01)); sc0[j] = lo + hi;
                f2_unpack(lo, hi, f2_add(a10, a11)); sc1[j] = lo + hi;
            }
            float gm0 = sc0[0], gm1 = sc1[0];
            #pragma unroll
            for (int j = 1; j < 8; j++) { gm0 = fmaxf(gm0, sc0[j]); gm1 = fmaxf(gm1, sc1[j]); }
            if (gm0 > m0) {
                float sf = __expf(m0 - gm0);   // m=-inf -> 0
                l0 *= sf;
                u64 s2 = f2_dup(sf);
                #pragma unroll
                for (int e = 0; e < 16; e++) Ov[0][e] = f2_mul(Ov[0][e], s2);
                m0 = gm0;
            }
            if (gm1 > m1) {
                float sf = __expf(m1 - gm1);
                l1 *= sf;
                u64 s2 = f2_dup(sf);
                #pragma unroll
                for (int e = 0; e < 16; e++) Ov[1][e] = f2_mul(Ov[1][e], s2);
                m1 = gm1;
            }
            #pragma unroll
            for (int j = 0; j < 8; j++) {
                float p0 = __expf(sc0[j] - m0); l0 += p0;
                float p1 = __expf(sc1[j] - m1); l1 += p1;
                u64 pp0 = f2_dup(p0);
                u64 pp1 = f2_dup(p1);
                const double2* Vr = (const double2*)&Vsm[(g * 8 + j) * 8];
                #pragma unroll
                for (int i = 0; i < 4; i++) {
                    double2 v0 = Vr[2 * i];
                    double2 v1 = Vr[2 * i + 1];
                    u64 x0 = __double_as_longlong(v0.x), x1 = __double_as_longlong(v0.y);
                    u64 x2 = __double_as_longlong(v1.x), x3 = __double_as_longlong(v1.y);
                    Ov[0][4 * i + 0] = f2_fma(pp0, x0, Ov[0][4 * i + 0]);
                    Ov[0][4 * i + 1] = f2_fma(pp0, x1, Ov[0][4 * i + 1]);
                    Ov[0][4 * i + 2] = f2_fma(pp0, x2, Ov[0][4 * i + 2]);
                    Ov[0][4 * i + 3] = f2_fma(pp0, x3, Ov[0][4 * i + 3]);
                    Ov[1][4 * i + 0] = f2_fma(pp1, x0, Ov[1][4 * i + 0]);
                    Ov[1][4 * i + 1] = f2_fma(pp1, x1, Ov[1][4 * i + 1]);
                    Ov[1][4 * i + 2] = f2_fma(pp1, x2, Ov[1][4 * i + 2]);
                    Ov[1][4 * i + 3] = f2_fma(pp1, x3, Ov[1][4 * i + 3]);
                }
            }
        }
    }
    #pragma unroll
    for (int s = 0; s < 2; s++) {
        size_t orow = view2 * QCNT + qt * 128 + s * 64 + tid;
        u64* dst = (u64*)(Opart + orow * DH);
        #pragma unroll
        for (int e = 0; e < 16; e++) dst[e] = Ov[s][e];
        ml[orow * 2]     = s ? m1 : m0;
        ml[orow * 2 + 1] = s ? l1 : l0;
    }
}

// ==================================================================
// Kernel 3: fused combine(12 partials) + out-proj + skip + preLN + MLP
//           + postLN + transposed store.  128 threads, 32-row tiles.
// ==================================================================
#define CTP 132
__global__ __launch_bounds__(128) void tail_kernel(
    const float* __restrict__ Opart, const float* __restrict__ ml,
    const float* __restrict__ skip,
    const float* __restrict__ Wpm, const float* __restrict__ bpv,
    const float* __restrict__ preg, const float* __restrict__ preb,
    const float* __restrict__ W1m, const float* __restrict__ b1v,
    const float* __restrict__ W2m, const float* __restrict__ b2v,
    const float* __restrict__ postg, const float* __restrict__ postb,
    float* __restrict__ outp)
{
    __shared__ float As[32 * CTP];
    __shared__ float Bs[32 * CTP];
    __shared__ float sW[128 * NPART];   // softmax-merge weights per (row,head)
    __shared__ float sm[32], sr[32];
    int tid = threadIdx.x;
    int gr0 = blockIdx.x * 32;          // rows are b*2304+q
    int b = gr0 / QCNT, q0 = gr0 - b * QCNT;

    // ---- stage combine weights: one thread per (row, head) ----
    {
        int r = tid >> 2, head = tid & 3;
        int q = q0 + r;
        size_t bhx = (size_t)b * HEADS + head;
        size_t rowbase = (bhx * NV * NSPLIT) * QCNT + q;
        float mv[NPART], lv[NPART], M = -CUDART_INF_F;
        #pragma unroll
        for (int n2 = 0; n2 < NPART; n2++) {
            size_t row = rowbase + (size_t)n2 * QCNT;
            mv[n2] = ml[row * 2];
            lv[n2] = ml[row * 2 + 1];
            M = fmaxf(M, mv[n2]);
        }
        float L = 0.f;
        float w[NPART];
        #pragma unroll
        for (int n2 = 0; n2 < NPART; n2++) {
            w[n2] = __expf(mv[n2] - M);
            L += w[n2] * lv[n2];
        }
        float Linv = __fdividef(1.f, L);
        #pragma unroll
        for (int n2 = 0; n2 < NPART; n2++)
            sW[tid * NPART + n2] = w[n2] * Linv;
    }
    __syncthreads();

    // ---- fused combine: merge 12 per-(view,split) partials into As ----
    for (int idx = tid; idx < 4096; idx += 128) {
        int r = idx >> 7, c = idx & 127;
        int q = q0 + r;
        int head = c >> 5, dh = c & 31;
        size_t bhx = (size_t)b * HEADS + head;
        const float* wv = &sW[(r * 4 + head) * NPART];
        size_t obase = ((bhx * NV * NSPLIT) * QCNT + q) * DH + dh;
        float o = 0.f;
        #pragma unroll
        for (int n2 = 0; n2 < NPART; n2++)
            o += wv[n2] * Opart[obase + (size_t)n2 * QCNT * DH];
        As[r * CTP + c] = o;
    }
    __syncthreads();

    int rg = tid >> 4, cg = tid & 15, c0 = cg * 8;   // rg 0..7 -> 4 rows each
    // ---- GEMM1: z = A @ Wp ----
    {
        u64 acc[4][4];
        #pragma unroll
        for (int i = 0; i < 4; i++)
            #pragma unroll
            for (int j = 0; j < 4; j++) acc[i][j] = 0ull;
        #pragma unroll 2
        for (int k = 0; k < 128; k++) {
            const double* Wd = (const double*)(Wpm + k * 128 + c0);
            u64 w0 = __double_as_longlong(Wd[0]);
            u64 w1 = __double_as_longlong(Wd[1]);
            u64 w2 = __double_as_longlong(Wd[2]);
            u64 w3 = __double_as_longlong(Wd[3]);
            #pragma unroll
            for (int i = 0; i < 4; i++) {
                u64 av = f2_dup(As[(4 * rg + i) * CTP + k]);
                acc[i][0] = f2_fma(av, w0, acc[i][0]);
                acc[i][1] = f2_fma(av, w1, acc[i][1]);
                acc[i][2] = f2_fma(av, w2, acc[i][2]);
                acc[i][3] = f2_fma(av, w3, acc[i][3]);
            }
        }
        const double* bd = (const double*)(bpv + c0);
        #pragma unroll
        for (int i = 0; i < 4; i++) {
            u64* dst = (u64*)&Bs[(4 * rg + i) * CTP + c0];
            #pragma unroll
            for (int j = 0; j < 4; j++)
                dst[j] = f2_add(acc[i][j], __double_as_longlong(bd[j]));
        }
    }
    __syncthreads();
    // ---- + skip (coalesced over spatial) ----
    for (int idx = tid; idx < 4096; idx += 128) {
        int c = idx >> 5, r = idx & 31;
        Bs[r * CTP + c] += skip[((size_t)(b * DIMC + c)) * QCNT + q0 + r];
    }
    __syncthreads();
    // ---- pre-LN ----
    if (tid < 32) {
        float s = 0.f, s2 = 0.f;
        const float* row = &Bs[tid * CTP];
        #pragma unroll 8
        for (int c = 0; c < 128; c++) { float x = row[c]; s += x; s2 += x * x; }
        float mn = s * (1.f / 128.f);
        float vv = s2 * (1.f / 128.f) - mn * mn;
        sm[tid] = mn; sr[tid] = rsqrtf(vv + 1e-5f);
    }
    __syncthreads();
    for (int idx = tid; idx < 4096; idx += 128) {
        int r = idx >> 7, c = idx & 127;
        Bs[r * CTP + c] = (Bs[r * CTP + c] - sm[r]) * sr[r] * preg[c] + preb[c];
    }
    __syncthreads();
    // ---- MLP: two column-halves of W1, accumulate GEMM2 into regs ----
    u64 acc2[4][4];
    #pragma unroll
    for (int i = 0; i < 4; i++)
        #pragma unroll
        for (int j = 0; j < 4; j++) acc2[i][j] = 0ull;
    for (int half = 0; half < 2; half++) {
        u64 h[4][4];
        #pragma unroll
        for (int i = 0; i < 4; i++)
            #pragma unroll
            for (int j = 0; j < 4; j++) h[i][j] = 0ull;
        #pragma unroll 2
        for (int k = 0; k < 128; k++) {
            const double* Wd = (const double*)(W1m + k * 256 + half * 128 + c0);
            u64 w0 = __double_as_longlong(Wd[0]);
            u64 w1 = __double_as_longlong(Wd[1]);
            u64 w2 = __double_as_longlong(Wd[2]);
            u64 w3 = __double_as_longlong(Wd[3]);
            #pragma unroll
            for (int i = 0; i < 4; i++) {
                u64 av = f2_dup(Bs[(4 * rg + i) * CTP + k]);
                h[i][0] = f2_fma(av, w0, h[i][0]);
                h[i][1] = f2_fma(av, w1, h[i][1]);
                h[i][2] = f2_fma(av, w2, h[i][2]);
                h[i][3] = f2_fma(av, w3, h[i][3]);
            }
        }
        const double* b1d = (const double*)(b1v + half * 128 + c0);
        #pragma unroll
        for (int i = 0; i < 4; i++)
            #pragma unroll
            for (int j = 0; j < 4; j++) {
                float lo, hi;
                f2_unpack(lo, hi, f2_add(h[i][j], __double_as_longlong(b1d[j])));
                float g0 = 0.5f * lo * (1.f + erff(lo * 0.70710678118654752f));
                float g1 = 0.5f * hi * (1.f + erff(hi * 0.70710678118654752f));
                As[(4 * rg + i) * CTP + c0 + 2 * j]     = g0;
                As[(4 * rg + i) * CTP + c0 + 2 * j + 1] = g1;
            }
        __syncthreads();
        #pragma unroll 2
        for (int k = 0; k < 128; k++) {
            const double* Wd = (const double*)(W2m + (half * 128 + k) * 128 + c0);
            u64 w0 = __double_as_longlong(Wd[0]);
            u64 w1 = __double_as_longlong(Wd[1]);
            u64 w2 = __double_as_longlong(Wd[2]);
            u64 w3 = __double_as_longlong(Wd[3]);
            #pragma unroll
            for (int i = 0; i < 4; i++) {
                u64 av = f2_dup(As[(4 * rg + i) * CTP + k]);
                acc2[i][0] = f2_fma(av, w0, acc2[i][0]);
                acc2[i][1] = f2_fma(av, w1, acc2[i][1]);
                acc2[i][2] = f2_fma(av, w2, acc2[i][2]);
                acc2[i][3] = f2_fma(av, w3, acc2[i][3]);
            }
        }
        __syncthreads();
    }
    {
        const double* b2d = (const double*)(b2v + c0);
        #pragma unroll
        for (int i = 0; i < 4; i++) {
            u64* dst = (u64*)&Bs[(4 * rg + i) * CTP + c0];
            #pragma unroll
            for (int j = 0; j < 4; j++)
                dst[j] = f2_add(dst[j], f2_add(acc2[i][j], __double_as_longlong(b2d[j])));
        }
    }
    __syncthreads();
    // ---- post-LN ----
    if (tid < 32) {
        float s = 0.f, s2 = 0.f;
        const float* row = &Bs[tid * CTP];
        #pragma unroll 8
        for (int c = 0; c < 128; c++) { float x = row[c]; s += x; s2 += x * x; }
        float mn = s * (1.f / 128.f);
        float vv = s2 * (1.f / 128.f) - mn * mn;
        sm[tid] = mn; sr[tid] = rsqrtf(vv + 1e-5f);
    }
    __syncthreads();
    // ---- write transposed output (B, d, H, W) ----
    for (int idx = tid; idx < 4096; idx += 128) {
        int c = idx >> 5, r = idx & 31;
        float z = (Bs[r * CTP + c] - sm[r]) * sr[r] * postg[c] + postb[c];
        outp[((size_t)(b * DIMC + c)) * QCNT + q0 + r] = z;
    }
}

// ==================================================================
extern "C" void kernel_launch(void* const* d_in, const int* in_sizes, int n_in,
                              void* d_out, int out_size)
{
    const float* q     = (const float*)d_in[0];
    const float* k     = (const float*)d_in[1];
    const float* v     = (const float*)d_in[2];
    const float* skip  = (const float*)d_in[3];
    const float* lnq_g = (const float*)d_in[4];
    const float* lnq_b = (const float*)d_in[5];
    const float* Wq    = (const float*)d_in[6];
    const float* bq    = (const float*)d_in[7];
    const float* lnk_g = (const float*)d_in[8];
    const float* lnk_b = (const float*)d_in[9];
    const float* Wk    = (const float*)d_in[10];
    const float* bk    = (const float*)d_in[11];
    const float* lnv_g = (const float*)d_in[12];
    const float* lnv_b = (const float*)d_in[13];
    const float* Wv    = (const float*)d_in[14];
    const float* bv    = (const float*)d_in[15];
    const float* Wp    = (const float*)d_in[16];
    const float* bp    = (const float*)d_in[17];
    const float* pre_g = (const float*)d_in[18];
    const float* pre_b = (const float*)d_in[19];
    const float* W1    = (const float*)d_in[20];
    const float* b1    = (const float*)d_in[21];
    const float* W2    = (const float*)d_in[22];
    const float* b2    = (const float*)d_in[23];
    const float* post_g= (const float*)d_in[24];
    const float* post_b= (const float*)d_in[25];
    float* outp = (float*)d_out;

    float *qp, *kpb, *vpb, *Opart, *mlb;
    cudaGetSymbolAddress((void**)&qp,   g_qp);
    cudaGetSymbolAddress((void**)&kpb,  g_kp);
    cudaGetSymbolAddress((void**)&vpb,  g_vp);
    cudaGetSymbolAddress((void**)&Opart,g_Opart);
    cudaGetSymbolAddress((void**)&mlb,  g_ml);

    const int PROJ_SMEM = 128 * PJS * sizeof(float);  // 66048
    cudaFuncSetAttribute(proj_all_kernel,
                         cudaFuncAttributeMaxDynamicSharedMemorySize, PROJ_SMEM);

    proj_all_kernel<<<432, 256, PROJ_SMEM>>>(q, k, v,
        lnq_g, lnq_b, Wq, bq, lnk_g, lnk_b, Wk, bk, lnv_g, lnv_b, Wv, bv,
        qp, kpb, vpb);

    dim3 ag(QCNT / 128, NPART, BH);
    attn_kernel<<<ag, 64>>>(qp, kpb, vpb, Opart, mlb);

    tail_kernel<<<(BB * QCNT) / 32, 128>>>(Opart, mlb, skip, Wp, bp, pre_g, pre_b,
                                           W1, b1, W2, b2, post_g, post_b, outp);
}

// round 5
// speedup vs baseline: 1.4586x; 1.4586x over previous
#include <cuda_runtime.h>
#include <math_constants.h>

// ---------------- problem constants ----------------
#define BB 2
#define NV 6
#define DIMC 128
#define QCNT 2304   // 48*48
#define KCNT 576    // 24*24
#define HEADS 4
#define DH 32
#define BH (BB*HEADS)          // 8
#define NSPLIT 2
#define KSPL (KCNT/NSPLIT)     // 288
#define NPART (NV*NSPLIT)      // 12
#define SCALEF 0.17677669529663689f  // 32^-0.5

typedef unsigned long long u64;

// ---------------- f32x2 packed helpers ----------------
__device__ __forceinline__ u64 f2_fma(u64 a, u64 b, u64 c) {
    u64 d; asm("fma.rn.f32x2 %0,%1,%2,%3;" : "=l"(d) : "l"(a), "l"(b), "l"(c)); return d;
}
__device__ __forceinline__ u64 f2_mul(u64 a, u64 b) {
    u64 d; asm("mul.rn.f32x2 %0,%1,%2;" : "=l"(d) : "l"(a), "l"(b)); return d;
}
__device__ __forceinline__ u64 f2_add(u64 a, u64 b) {
    u64 d; asm("add.rn.f32x2 %0,%1,%2;" : "=l"(d) : "l"(a), "l"(b)); return d;
}
__device__ __forceinline__ u64 f2_dup(float x) {
    u64 d; asm("mov.b64 %0,{%1,%1};" : "=l"(d) : "r"(__float_as_uint(x))); return d;
}
__device__ __forceinline__ void f2_unpack(float& lo, float& hi, u64 v) {
    unsigned a, b; asm("mov.b64 {%0,%1},%2;" : "=r"(a), "=r"(b) : "l"(v));
    lo = __uint_as_float(a); hi = __uint_as_float(b);
}
__device__ __forceinline__ unsigned s2u(const void* p) {
    unsigned r;
    asm("{.reg .u64 t; cvta.to.shared.u64 t, %1; cvt.u32.u64 %0, t;}" : "=r"(r) : "l"(p));
    return r;
}
__device__ __forceinline__ void cpa16(unsigned s, const void* g) {
    asm volatile("cp.async.cg.shared.global [%0], [%1], 16;" :: "r"(s), "l"(g));
}

// ---------------- scratch (device globals; no allocation allowed) ----------------
__device__ float g_qp[BH * NV * QCNT * DH];
__device__ float g_kp[BH * NV * KCNT * DH];
__device__ float g_vp[BH * NV * KCNT * DH];
__device__ float g_Opart[BH * NPART * QCNT * DH];
__device__ float g_ml[BH * NPART * QCNT * 2];

// ==================================================================
// Kernel 1: LN + projection for q,k,v in ONE launch. 64-row tiles.
// q: blocks [0,432), k: [432,540), v: [540,648).  256 threads.
// Dynamic smem: As[64*129] + Wsm[128*128]  = 98560 B (2 blocks/SM)
// q output is pre-scaled by SCALEF.
// ==================================================================
#define PJS 129
__global__ __launch_bounds__(256) void proj_all_kernel(
    const float* __restrict__ qi, const float* __restrict__ ki, const float* __restrict__ vi,
    const float* __restrict__ lnqg, const float* __restrict__ lnqb,
    const float* __restrict__ Wq, const float* __restrict__ bq,
    const float* __restrict__ lnkg, const float* __restrict__ lnkb,
    const float* __restrict__ Wk, const float* __restrict__ bk,
    const float* __restrict__ lnvg, const float* __restrict__ lnvb,
    const float* __restrict__ Wv, const float* __restrict__ bv,
    float* __restrict__ qo, float* __restrict__ ko, float* __restrict__ vo)
{
    extern __shared__ float dynP[];
    float* As  = dynP;                  // 64*129
    float* Wsm = dynP + 64 * PJS;       // 128*128
    __shared__ float s_mean[64], s_rstd[64];
    int blk = blockIdx.x;
    int tid = threadIdx.x;

    const float* X; const float* lng; const float* lnb;
    const float* Wt; const float* biasv; float* outp; int S, local; float oscale;
    if (blk < 432)      { X = qi; lng = lnqg; lnb = lnqb; Wt = Wq; biasv = bq; outp = qo; S = QCNT; local = blk;       oscale = SCALEF; }
    else if (blk < 540) { X = ki; lng = lnkg; lnb = lnkb; Wt = Wk; biasv = bk; outp = ko; S = KCNT; local = blk - 432; oscale = 1.f; }
    else                { X = vi; lng = lnvg; lnb = lnvb; Wt = Wv; biasv = bv; outp = vo; S = KCNT; local = blk - 540; oscale = 1.f; }

    int tiles = S >> 6;
    int t = local % tiles;
    int bn = local / tiles;            // b*6+n
    int b = bn / NV, n = bn % NV;
    int s0 = t * 64;
    const float* Xb = X + (size_t)bn * DIMC * S;

    // load A tile (coalesced: consecutive tid -> consecutive spatial)
    for (int idx = tid; idx < 64 * 128; idx += 256) {
        int c = idx >> 6, r = idx & 63;
        As[r * PJS + c] = Xb[(size_t)c * S + s0 + r];
    }
    // stage full weight matrix into smem
    {
        const float4* Wg = (const float4*)Wt;
        float4* Ws4 = (float4*)Wsm;
        for (int i = tid; i < 4096; i += 256) Ws4[i] = Wg[i];
    }
    __syncthreads();
    if (tid < 64) {
        float s = 0.f, s2 = 0.f;
        const float* row = &As[tid * PJS];
        #pragma unroll 8
        for (int c = 0; c < 128; c++) { float x = row[c]; s += x; s2 += x * x; }
        float mn = s * (1.f / 128.f);
        float vv = s2 * (1.f / 128.f) - mn * mn;
        s_mean[tid] = mn; s_rstd[tid] = rsqrtf(vv + 1e-5f);
    }
    __syncthreads();
    for (int idx = tid; idx < 64 * 128; idx += 256) {
        int r = idx >> 7, c = idx & 127;
        As[r * PJS + c] = (As[r * PJS + c] - s_mean[r]) * s_rstd[r] * lng[c] + lnb[c];
    }
    __syncthreads();

    // GEMM 64x128 * 128x128, per-thread 4 rows x 8 cols, all smem operands
    int rg = tid >> 4;        // 0..15
    int c0 = (tid & 15) * 8;
    u64 acc[4][4];
    #pragma unroll
    for (int i = 0; i < 4; i++)
        #pragma unroll
        for (int j = 0; j < 4; j++) acc[i][j] = 0ull;

    #pragma unroll 2
    for (int k = 0; k < 128; k++) {
        const double* Wd = (const double*)(Wsm + k * 128 + c0);
        u64 w0 = __double_as_longlong(Wd[0]);
        u64 w1 = __double_as_longlong(Wd[1]);
        u64 w2 = __double_as_longlong(Wd[2]);
        u64 w3 = __double_as_longlong(Wd[3]);
        #pragma unroll
        for (int i = 0; i < 4; i++) {
            u64 av = f2_dup(As[(4 * rg + i) * PJS + k]);
            acc[i][0] = f2_fma(av, w0, acc[i][0]);
            acc[i][1] = f2_fma(av, w1, acc[i][1]);
            acc[i][2] = f2_fma(av, w2, acc[i][2]);
            acc[i][3] = f2_fma(av, w3, acc[i][3]);
        }
    }
    const double* Bd = (const double*)(biasv + c0);
    u64 bb0 = __double_as_longlong(Bd[0]);
    u64 bb1 = __double_as_longlong(Bd[1]);
    u64 bb2 = __double_as_longlong(Bd[2]);
    u64 bb3 = __double_as_longlong(Bd[3]);
    u64 sc = f2_dup(oscale);
    int head = c0 >> 5, dh0 = c0 & 31;
    #pragma unroll
    for (int i = 0; i < 4; i++) {
        int qrow = s0 + 4 * rg + i;
        u64* dst = (u64*)(outp + ((((size_t)(b * HEADS + head) * NV + n) * S + qrow) * DH + dh0));
        dst[0] = f2_mul(f2_add(acc[i][0], bb0), sc);
        dst[1] = f2_mul(f2_add(acc[i][1], bb1), sc);
        dst[2] = f2_mul(f2_add(acc[i][2], bb2), sc);
        dst[3] = f2_mul(f2_add(acc[i][3], bb3), sc);
    }
}

// ==================================================================
// Kernel 2: per-(view,split) flash attention partials. 2 queries/thread.
// grid (18, 12, 8), 64 threads. 288 keys in 3x96 chunks, cp.async
// double-buffered (2 stages x (K+V) x 96 rows = 48KB smem).
// ==================================================================
__device__ __forceinline__ void attn_chunk(
    const float4* Ks, const float4* Vs,
    const u64 qu[2][16], u64 Ov[2][16],
    float& m0, float& m1, float& l0, float& l1)
{
    #pragma unroll 1
    for (int g = 0; g < 12; g++) {
        float sc0[8], sc1[8];
        #pragma unroll
        for (int j = 0; j < 8; j++) {
            const double2* Kr = (const double2*)&Ks[(g * 8 + j) * 8];
            u64 a00 = 0, a01 = 0, a10 = 0, a11 = 0;
            #pragma unroll
            for (int i = 0; i < 4; i++) {
                double2 d0 = Kr[2 * i];
                double2 d1 = Kr[2 * i + 1];
                u64 k0 = __double_as_longlong(d0.x), k1 = __double_as_longlong(d0.y);
                u64 k2 = __double_as_longlong(d1.x), k3 = __double_as_longlong(d1.y);
                a00 = f2_fma(qu[0][4 * i + 0], k0, a00);
                a01 = f2_fma(qu[0][4 * i + 1], k1, a01);
                a00 = f2_fma(qu[0][4 * i + 2], k2, a00);
                a01 = f2_fma(qu[0][4 * i + 3], k3, a01);
                a10 = f2_fma(qu[1][4 * i + 0], k0, a10);
                a11 = f2_fma(qu[1][4 * i + 1], k1, a11);
                a10 = f2_fma(qu[1][4 * i + 2], k2, a10);
                a11 = f2_fma(qu[1][4 * i + 3], k3, a11);
            }
            float lo, hi;
            f2_unpack(lo, hi, f2_add(a00, a01)); sc0[j] = lo + hi;
            f2_unpack(lo, hi, f2_add(a10, a11)); sc1[j] = lo + hi;
        }
        float gm0 = sc0[0], gm1 = sc1[0];
        #pragma unroll
        for (int j = 1; j < 8; j++) { gm0 = fmaxf(gm0, sc0[j]); gm1 = fmaxf(gm1, sc1[j]); }
        if (gm0 > m0) {
            float sf = __expf(m0 - gm0);   // m=-inf -> 0
            l0 *= sf;
            u64 s2 = f2_dup(sf);
            #pragma unroll
            for (int e = 0; e < 16; e++) Ov[0][e] = f2_mul(Ov[0][e], s2);
            m0 = gm0;
        }
        if (gm1 > m1) {
            float sf = __expf(m1 - gm1);
            l1 *= sf;
            u64 s2 = f2_dup(sf);
            #pragma unroll
            for (int e = 0; e < 16; e++) Ov[1][e] = f2_mul(Ov[1][e], s2);
            m1 = gm1;
        }
        #pragma unroll
        for (int j = 0; j < 8; j++) {
            float p0 = __expf(sc0[j] - m0); l0 += p0;
            float p1 = __expf(sc1[j] - m1); l1 += p1;
            u64 pp0 = f2_dup(p0);
            u64 pp1 = f2_dup(p1);
            const double2* Vr = (const double2*)&Vs[(g * 8 + j) * 8];
            #pragma unroll
            for (int i = 0; i < 4; i++) {
                double2 v0 = Vr[2 * i];
                double2 v1 = Vr[2 * i + 1];
                u64 x0 = __double_as_longlong(v0.x), x1 = __double_as_longlong(v0.y);
                u64 x2 = __double_as_longlong(v1.x), x3 = __double_as_longlong(v1.y);
                Ov[0][4 * i + 0] = f2_fma(pp0, x0, Ov[0][4 * i + 0]);
                Ov[0][4 * i + 1] = f2_fma(pp0, x1, Ov[0][4 * i + 1]);
                Ov[0][4 * i + 2] = f2_fma(pp0, x2, Ov[0][4 * i + 2]);
                Ov[0][4 * i + 3] = f2_fma(pp0, x3, Ov[0][4 * i + 3]);
                Ov[1][4 * i + 0] = f2_fma(pp1, x0, Ov[1][4 * i + 0]);
                Ov[1][4 * i + 1] = f2_fma(pp1, x1, Ov[1][4 * i + 1]);
                Ov[1][4 * i + 2] = f2_fma(pp1, x2, Ov[1][4 * i + 2]);
                Ov[1][4 * i + 3] = f2_fma(pp1, x3, Ov[1][4 * i + 3]);
            }
        }
    }
}

__global__ __launch_bounds__(64) void attn_kernel(
    const float* __restrict__ qp, const float* __restrict__ kp,
    const float* __restrict__ vp, float* __restrict__ Opart,
    float* __restrict__ ml)
{
    __shared__ float4 Ksm[2][768];
    __shared__ float4 Vsm[2][768];
    int qt = blockIdx.x;
    int ns = blockIdx.y;                 // n*2 + split
    int bh = blockIdx.z;
    int n = ns >> 1, split = ns & 1;
    int tid = threadIdx.x;
    size_t view = (size_t)bh * NV + n;
    size_t view2 = view * NSPLIT + split;
    int base = split * KSPL;

    const float4* Kb = (const float4*)(kp + view * KCNT * DH);
    const float4* Vb = (const float4*)(vp + view * KCNT * DH);

    // issue a 96-key (K,V) stage into buffer buf
    auto issue = [&](int st, int buf) {
        const float4* Kg = Kb + (size_t)(base + st * 96) * 8;
        const float4* Vg = Vb + (size_t)(base + st * 96) * 8;
        #pragma unroll
        for (int i = 0; i < 12; i++) {
            int f = i * 64 + tid;
            cpa16(s2u(&Ksm[buf][f]), Kg + f);
            cpa16(s2u(&Vsm[buf][f]), Vg + f);
        }
        asm volatile("cp.async.commit_group;");
    };

    issue(0, 0);
    issue(1, 1);

    u64 qu[2][16];
    #pragma unroll
    for (int s = 0; s < 2; s++) {
        const u64* qrow = (const u64*)(qp + (view * QCNT + qt * 128 + s * 64 + tid) * DH);
        #pragma unroll
        for (int e = 0; e < 16; e++) qu[s][e] = qrow[e];   // pre-scaled by SCALEF
    }
    u64 Ov[2][16];
    #pragma unroll
    for (int s = 0; s < 2; s++)
        #pragma unroll
        for (int e = 0; e < 16; e++) Ov[s][e] = 0ull;
    float m0 = -CUDART_INF_F, m1 = -CUDART_INF_F, l0 = 0.f, l1 = 0.f;

    asm volatile("cp.async.wait_group 1;");
    __syncthreads();
    attn_chunk(Ksm[0], Vsm[0], qu, Ov, m0, m1, l0, l1);
    __syncthreads();
    issue(2, 0);
    asm volatile("cp.async.wait_group 1;");
    __syncthreads();
    attn_chunk(Ksm[1], Vsm[1], qu, Ov, m0, m1, l0, l1);
    __syncthreads();
    asm volatile("cp.async.wait_group 0;");
    __syncthreads();
    attn_chunk(Ksm[0], Vsm[0], qu, Ov, m0, m1, l0, l1);

    #pragma unroll
    for (int s = 0; s < 2; s++) {
        size_t orow = view2 * QCNT + qt * 128 + s * 64 + tid;
        u64* dst = (u64*)(Opart + orow * DH);
        #pragma unroll
        for (int e = 0; e < 16; e++) dst[e] = Ov[s][e];
        ml[orow * 2]     = s ? m1 : m0;
        ml[orow * 2 + 1] = s ? l1 : l0;
    }
}

// ==================================================================
// Kernel 3: fused combine(12) + out-proj + skip + preLN + MLP + postLN
//           + transposed store.  256 threads, 32-row tiles.
// Dynamic smem: As + Bs (32x132 each) + Wsm(128x128) + sW(128x12)
// ==================================================================
#define CTP 132
__global__ __launch_bounds__(256) void tail_kernel(
    const float* __restrict__ Opart, const float* __restrict__ ml,
    const float* __restrict__ skip,
    const float* __restrict__ Wpm, const float* __restrict__ bpv,
    const float* __restrict__ preg, const float* __restrict__ preb,
    const float* __restrict__ W1m, const float* __restrict__ b1v,
    const float* __restrict__ W2m, const float* __restrict__ b2v,
    const float* __restrict__ postg, const float* __restrict__ postb,
    float* __restrict__ outp)
{
    extern __shared__ float dynT[];
    float* As  = dynT;                       // 32*CTP
    float* Bs  = As + 32 * CTP;              // 32*CTP
    float* Wsm = Bs + 32 * CTP;              // 16384
    float* sW  = Wsm + 16384;                // 128*NPART
    __shared__ float sm[32], sr[32];
    int tid = threadIdx.x;
    int gr0 = blockIdx.x * 32;          // rows are b*2304+q
    int b = gr0 / QCNT, q0 = gr0 - b * QCNT;

    // ---- stage combine weights: one thread per (row, head) ----
    if (tid < 128) {
        int r = tid >> 2, head = tid & 3;
        int q = q0 + r;
        size_t bhx = (size_t)b * HEADS + head;
        size_t rowbase = (bhx * NPART) * QCNT + q;
        float mv[NPART], lv[NPART], M = -CUDART_INF_F;
        #pragma unroll
        for (int n2 = 0; n2 < NPART; n2++) {
            size_t row = rowbase + (size_t)n2 * QCNT;
            mv[n2] = ml[row * 2];
            lv[n2] = ml[row * 2 + 1];
            M = fmaxf(M, mv[n2]);
        }
        float L = 0.f;
        float w[NPART];
        #pragma unroll
        for (int n2 = 0; n2 < NPART; n2++) {
            w[n2] = __expf(mv[n2] - M);
            L += w[n2] * lv[n2];
        }
        float Linv = __fdividef(1.f, L);
        #pragma unroll
        for (int n2 = 0; n2 < NPART; n2++)
            sW[tid * NPART + n2] = w[n2] * Linv;
    }
    __syncthreads();

    // ---- combine 12 partials into As; stage Wp into Wsm ----
    for (int idx = tid; idx < 4096; idx += 256) {
        int r = idx >> 7, c = idx & 127;
        int q = q0 + r;
        int head = c >> 5, dh = c & 31;
        size_t bhx = (size_t)b * HEADS + head;
        const float* wv = &sW[(r * 4 + head) * NPART];
        size_t obase = ((bhx * NPART) * QCNT + q) * DH + dh;
        float o = 0.f;
        #pragma unroll
        for (int n2 = 0; n2 < NPART; n2++)
            o += wv[n2] * Opart[obase + (size_t)n2 * QCNT * DH];
        As[r * CTP + c] = o;
    }
    {
        const float4* g = (const float4*)Wpm;
        float4* d = (float4*)Wsm;
        for (int i = tid; i < 4096; i += 256) d[i] = g[i];
    }
    __syncthreads();

    int rg = tid >> 4, c0 = (tid & 15) * 8;   // rg 0..15 -> 2 rows each
    // ---- GEMM1: z = A @ Wp ----
    {
        u64 acc[2][4];
        #pragma unroll
        for (int i = 0; i < 2; i++)
            #pragma unroll
            for (int j = 0; j < 4; j++) acc[i][j] = 0ull;
        #pragma unroll 2
        for (int k = 0; k < 128; k++) {
            const double* Wd = (const double*)(Wsm + k * 128 + c0);
            u64 w0 = __double_as_longlong(Wd[0]);
            u64 w1 = __double_as_longlong(Wd[1]);
            u64 w2 = __double_as_longlong(Wd[2]);
            u64 w3 = __double_as_longlong(Wd[3]);
            #pragma unroll
            for (int i = 0; i < 2; i++) {
                u64 av = f2_dup(As[(2 * rg + i) * CTP + k]);
                acc[i][0] = f2_fma(av, w0, acc[i][0]);
                acc[i][1] = f2_fma(av, w1, acc[i][1]);
                acc[i][2] = f2_fma(av, w2, acc[i][2]);
                acc[i][3] = f2_fma(av, w3, acc[i][3]);
            }
        }
        const double* bd = (const double*)(bpv + c0);
        #pragma unroll
        for (int i = 0; i < 2; i++) {
            u64* dst = (u64*)&Bs[(2 * rg + i) * CTP + c0];
            #pragma unroll
            for (int j = 0; j < 4; j++)
                dst[j] = f2_add(acc[i][j], __double_as_longlong(bd[j]));
        }
    }
    __syncthreads();
    // ---- + skip, and stage W1 half0 into Wsm ----
    for (int idx = tid; idx < 4096; idx += 256) {
        int c = idx >> 5, r = idx & 31;
        Bs[r * CTP + c] += skip[((size_t)(b * DIMC + c)) * QCNT + q0 + r];
    }
    for (int i = tid; i < 4096; i += 256) {
        int k = i >> 5, c4 = i & 31;
        ((float4*)Wsm)[k * 32 + c4] = ((const float4*)(W1m + k * 256))[c4];
    }
    __syncthreads();
    // ---- pre-LN ----
    if (tid < 32) {
        float s = 0.f, s2 = 0.f;
        const float* row = &Bs[tid * CTP];
        #pragma unroll 8
        for (int c = 0; c < 128; c++) { float x = row[c]; s += x; s2 += x * x; }
        float mn = s * (1.f / 128.f);
        float vv = s2 * (1.f / 128.f) - mn * mn;
        sm[tid] = mn; sr[tid] = rsqrtf(vv + 1e-5f);
    }
    __syncthreads();
    for (int idx = tid; idx < 4096; idx += 256) {
        int r = idx >> 7, c = idx & 127;
        Bs[r * CTP + c] = (Bs[r * CTP + c] - sm[r]) * sr[r] * preg[c] + preb[c];
    }
    __syncthreads();
    // ---- MLP: two column-halves of W1/W2, weights staged through Wsm ----
    u64 acc2[2][4];
    #pragma unroll
    for (int i = 0; i < 2; i++)
        #pragma unroll
        for (int j = 0; j < 4; j++) acc2[i][j] = 0ull;
    #pragma unroll 1
    for (int half = 0; half < 2; half++) {
        // (Wsm holds W1 half on loop entry)
        u64 h[2][4];
        #pragma unroll
        for (int i = 0; i < 2; i++)
            #pragma unroll
            for (int j = 0; j < 4; j++) h[i][j] = 0ull;
        #pragma unroll 2
        for (int k = 0; k < 128; k++) {
            const double* Wd = (const double*)(Wsm + k * 128 + c0);
            u64 w0 = __double_as_longlong(Wd[0]);
            u64 w1 = __double_as_longlong(Wd[1]);
            u64 w2 = __double_as_longlong(Wd[2]);
            u64 w3 = __double_as_longlong(Wd[3]);
            #pragma unroll
            for (int i = 0; i < 2; i++) {
                u64 av = f2_dup(Bs[(2 * rg + i) * CTP + k]);
                h[i][0] = f2_fma(av, w0, h[i][0]);
                h[i][1] = f2_fma(av, w1, h[i][1]);
                h[i][2] = f2_fma(av, w2, h[i][2]);
                h[i][3] = f2_fma(av, w3, h[i][3]);
            }
        }
        const double* b1d = (const double*)(b1v + half * 128 + c0);
        #pragma unroll
        for (int i = 0; i < 2; i++)
            #pragma unroll
            for (int j = 0; j < 4; j++) {
                float lo, hi;
                f2_unpack(lo, hi, f2_add(h[i][j], __double_as_longlong(b1d[j])));
                float g0 = 0.5f * lo * (1.f + erff(lo * 0.70710678118654752f));
                float g1 = 0.5f * hi * (1.f + erff(hi * 0.70710678118654752f));
                As[(2 * rg + i) * CTP + c0 + 2 * j]     = g0;
                As[(2 * rg + i) * CTP + c0 + 2 * j + 1] = g1;
            }
        __syncthreads();
        // stage W2 half (contiguous block of 16384 floats)
        {
            const float4* g = (const float4*)(W2m + half * 16384);
            float4* d = (float4*)Wsm;
            for (int i = tid; i < 4096; i += 256) d[i] = g[i];
        }
        __syncthreads();
        #pragma unroll 2
        for (int k = 0; k < 128; k++) {
            const double* Wd = (const double*)(Wsm + k * 128 + c0);
            u64 w0 = __double_as_longlong(Wd[0]);
            u64 w1 = __double_as_longlong(Wd[1]);
            u64 w2 = __double_as_longlong(Wd[2]);
            u64 w3 = __double_as_longlong(Wd[3]);
            #pragma unroll
            for (int i = 0; i < 2; i++) {
                u64 av = f2_dup(As[(2 * rg + i) * CTP + k]);
                acc2[i][0] = f2_fma(av, w0, acc2[i][0]);
                acc2[i][1] = f2_fma(av, w1, acc2[i][1]);
                acc2[i][2] = f2_fma(av, w2, acc2[i][2]);
                acc2[i][3] = f2_fma(av, w3, acc2[i][3]);
            }
        }
        __syncthreads();
        if (half == 0) {
            // stage W1 half1 for next iteration
            for (int i = tid; i < 4096; i += 256) {
                int k = i >> 5, c4 = i & 31;
                ((float4*)Wsm)[k * 32 + c4] = ((const float4*)(W1m + k * 256 + 128))[c4];
            }
            __syncthreads();
        }
    }
    {
        const double* b2d = (const double*)(b2v + c0);
        #pragma unroll
        for (int i = 0; i < 2; i++) {
            u64* dst = (u64*)&Bs[(2 * rg + i) * CTP + c0];
            #pragma unroll
            for (int j = 0; j < 4; j++)
                dst[j] = f2_add(dst[j], f2_add(acc2[i][j], __double_as_longlong(b2d[j])));
        }
    }
    __syncthreads();
    // ---- post-LN ----
    if (tid < 32) {
        float s = 0.f, s2 = 0.f;
        const float* row = &Bs[tid * CTP];
        #pragma unroll 8
        for (int c = 0; c < 128; c++) { float x = row[c]; s += x; s2 += x * x; }
        float mn = s * (1.f / 128.f);
        float vv = s2 * (1.f / 128.f) - mn * mn;
        sm[tid] = mn; sr[tid] = rsqrtf(vv + 1e-5f);
    }
    __syncthreads();
    // ---- write transposed output (B, d, H, W) ----
    for (int idx = tid; idx < 4096; idx += 256) {
        int c = idx >> 5, r = idx & 31;
        float z = (Bs[r * CTP + c] - sm[r]) * sr[r] * postg[c] + postb[c];
        outp[((size_t)(b * DIMC + c)) * QCNT + q0 + r] = z;
    }
}

// ==================================================================
extern "C" void kernel_launch(void* const* d_in, const int* in_sizes, int n_in,
                              void* d_out, int out_size)
{
    const float* q     = (const float*)d_in[0];
    const float* k     = (const float*)d_in[1];
    const float* v     = (const float*)d_in[2];
    const float* skip  = (const float*)d_in[3];
    const float* lnq_g = (const float*)d_in[4];
    const float* lnq_b = (const float*)d_in[5];
    const float* Wq    = (const float*)d_in[6];
    const float* bq    = (const float*)d_in[7];
    const float* lnk_g = (const float*)d_in[8];
    const float* lnk_b = (const float*)d_in[9];
    const float* Wk    = (const float*)d_in[10];
    const float* bk    = (const float*)d_in[11];
    const float* lnv_g = (const float*)d_in[12];
    const float* lnv_b = (const float*)d_in[13];
    const float* Wv    = (const float*)d_in[14];
    const float* bv    = (const float*)d_in[15];
    const float* Wp    = (const float*)d_in[16];
    const float* bp    = (const float*)d_in[17];
    const float* pre_g = (const float*)d_in[18];
    const float* pre_b = (const float*)d_in[19];
    const float* W1    = (const float*)d_in[20];
    const float* b1    = (const float*)d_in[21];
    const float* W2    = (const float*)d_in[22];
    const float* b2    = (const float*)d_in[23];
    const float* post_g= (const float*)d_in[24];
    const float* post_b= (const float*)d_in[25];
    float* outp = (float*)d_out;

    float *qp, *kpb, *vpb, *Opart, *mlb;
    cudaGetSymbolAddress((void**)&qp,   g_qp);
    cudaGetSymbolAddress((void**)&kpb,  g_kp);
    cudaGetSymbolAddress((void**)&vpb,  g_vp);
    cudaGetSymbolAddress((void**)&Opart,g_Opart);
    cudaGetSymbolAddress((void**)&mlb,  g_ml);

    const int PROJ_SMEM = (64 * PJS + 128 * 128) * sizeof(float);           // 98560
    const int TAIL_SMEM = (2 * 32 * CTP + 16384 + 128 * NPART) * sizeof(float); // 105472
    cudaFuncSetAttribute(proj_all_kernel,
                         cudaFuncAttributeMaxDynamicSharedMemorySize, PROJ_SMEM);
    cudaFuncSetAttribute(tail_kernel,
                         cudaFuncAttributeMaxDynamicSharedMemorySize, TAIL_SMEM);

    proj_all_kernel<<<648, 256, PROJ_SMEM>>>(q, k, v,
        lnq_g, lnq_b, Wq, bq, lnk_g, lnk_b, Wk, bk, lnv_g, lnv_b, Wv, bv,
        qp, kpb, vpb);

    dim3 ag(QCNT / 128, NPART, BH);
    attn_kernel<<<ag, 64>>>(qp, kpb, vpb, Opart, mlb);

    tail_kernel<<<(BB * QCNT) / 32, 256, TAIL_SMEM>>>(Opart, mlb, skip, Wp, bp, pre_g, pre_b,
                                           W1, b1, W2, b2, post_g, post_b, outp);
}

// round 6
// speedup vs baseline: 1.4997x; 1.0282x over previous
#include <cuda_runtime.h>
#include <math_constants.h>

// ---------------- problem constants ----------------
#define BB 2
#define NV 6
#define DIMC 128
#define QCNT 2304   // 48*48
#define KCNT 576    // 24*24
#define HEADS 4
#define DH 32
#define BH (BB*HEADS)          // 8
#define NSPLIT 2
#define KSPL (KCNT/NSPLIT)     // 288
#define NPART (NV*NSPLIT)      // 12
#define CHK 72                 // attn chunk keys
#define SCALEF 0.17677669529663689f  // 32^-0.5

typedef unsigned long long u64;

// ---------------- f32x2 packed helpers ----------------
__device__ __forceinline__ u64 f2_fma(u64 a, u64 b, u64 c) {
    u64 d; asm("fma.rn.f32x2 %0,%1,%2,%3;" : "=l"(d) : "l"(a), "l"(b), "l"(c)); return d;
}
__device__ __forceinline__ u64 f2_mul(u64 a, u64 b) {
    u64 d; asm("mul.rn.f32x2 %0,%1,%2;" : "=l"(d) : "l"(a), "l"(b)); return d;
}
__device__ __forceinline__ u64 f2_add(u64 a, u64 b) {
    u64 d; asm("add.rn.f32x2 %0,%1,%2;" : "=l"(d) : "l"(a), "l"(b)); return d;
}
__device__ __forceinline__ u64 f2_dup(float x) {
    u64 d; asm("mov.b64 %0,{%1,%1};" : "=l"(d) : "r"(__float_as_uint(x))); return d;
}
__device__ __forceinline__ void f2_unpack(float& lo, float& hi, u64 v) {
    unsigned a, b; asm("mov.b64 {%0,%1},%2;" : "=r"(a), "=r"(b) : "l"(v));
    lo = __uint_as_float(a); hi = __uint_as_float(b);
}
__device__ __forceinline__ unsigned s2u(const void* p) {
    unsigned r;
    asm("{.reg .u64 t; cvta.to.shared.u64 t, %1; cvt.u32.u64 %0, t;}" : "=r"(r) : "l"(p));
    return r;
}
__device__ __forceinline__ void cpa16(unsigned s, const void* g) {
    asm volatile("cp.async.cg.shared.global [%0], [%1], 16;" :: "r"(s), "l"(g));
}

// ---------------- scratch (device globals; no allocation allowed) ----------------
__device__ float g_qp[BH * NV * QCNT * DH];
__device__ float g_kp[BH * NV * KCNT * DH];
__device__ float g_vp[BH * NV * KCNT * DH];
__device__ float g_Opart[BH * NPART * QCNT * DH];
__device__ float g_ml[BH * NPART * QCNT * 2];

// ==================================================================
// Kernel 1: LN + projection for q,k,v in ONE launch. 64-row tiles.
// q: blocks [0,432), k: [432,540), v: [540,648).  256 threads.
// Dynamic smem: As[64*129] + Wsm[128*128] = 98560 B.
// Thread map: rg = tid&15 (rows), cg = tid>>4 (cols) -> W loads broadcast.
// q output pre-scaled by SCALEF.
// ==================================================================
#define PJS 129
__global__ __launch_bounds__(256) void proj_all_kernel(
    const float* __restrict__ qi, const float* __restrict__ ki, const float* __restrict__ vi,
    const float* __restrict__ lnqg, const float* __restrict__ lnqb,
    const float* __restrict__ Wq, const float* __restrict__ bq,
    const float* __restrict__ lnkg, const float* __restrict__ lnkb,
    const float* __restrict__ Wk, const float* __restrict__ bk,
    const float* __restrict__ lnvg, const float* __restrict__ lnvb,
    const float* __restrict__ Wv, const float* __restrict__ bv,
    float* __restrict__ qo, float* __restrict__ ko, float* __restrict__ vo)
{
    extern __shared__ float dynP[];
    float* As  = dynP;                  // 64*129
    float* Wsm = dynP + 64 * PJS;       // 128*128
    __shared__ float s_mean[64], s_rstd[64];
    int blk = blockIdx.x;
    int tid = threadIdx.x;

    const float* X; const float* lng; const float* lnb;
    const float* Wt; const float* biasv; float* outp; int S, local; float oscale;
    if (blk < 432)      { X = qi; lng = lnqg; lnb = lnqb; Wt = Wq; biasv = bq; outp = qo; S = QCNT; local = blk;       oscale = SCALEF; }
    else if (blk < 540) { X = ki; lng = lnkg; lnb = lnkb; Wt = Wk; biasv = bk; outp = ko; S = KCNT; local = blk - 432; oscale = 1.f; }
    else                { X = vi; lng = lnvg; lnb = lnvb; Wt = Wv; biasv = bv; outp = vo; S = KCNT; local = blk - 540; oscale = 1.f; }

    int tiles = S >> 6;
    int t = local % tiles;
    int bn = local / tiles;            // b*6+n
    int b = bn / NV, n = bn % NV;
    int s0 = t * 64;
    const float* Xb = X + (size_t)bn * DIMC * S;

    // load A tile (coalesced: consecutive tid -> consecutive spatial)
    for (int idx = tid; idx < 64 * 128; idx += 256) {
        int c = idx >> 6, r = idx & 63;
        As[r * PJS + c] = Xb[(size_t)c * S + s0 + r];
    }
    // stage full weight matrix into smem
    {
        const float4* Wg = (const float4*)Wt;
        float4* Ws4 = (float4*)Wsm;
        for (int i = tid; i < 4096; i += 256) Ws4[i] = Wg[i];
    }
    __syncthreads();
    // ---- LN stats: 4 threads per row, shfl butterfly ----
    {
        int r = tid >> 2, p = tid & 3;
        const float* row = &As[r * PJS];
        float s = 0.f, s2 = 0.f;
        #pragma unroll 8
        for (int ci = 0; ci < 32; ci++) { float x = row[p + 4 * ci]; s += x; s2 += x * x; }
        s  += __shfl_xor_sync(0xffffffffu, s, 1);
        s2 += __shfl_xor_sync(0xffffffffu, s2, 1);
        s  += __shfl_xor_sync(0xffffffffu, s, 2);
        s2 += __shfl_xor_sync(0xffffffffu, s2, 2);
        if (p == 0) {
            float mn = s * (1.f / 128.f);
            float vv = s2 * (1.f / 128.f) - mn * mn;
            s_mean[r] = mn; s_rstd[r] = rsqrtf(vv + 1e-5f);
        }
    }
    __syncthreads();
    for (int idx = tid; idx < 64 * 128; idx += 256) {
        int r = idx >> 7, c = idx & 127;
        As[r * PJS + c] = (As[r * PJS + c] - s_mean[r]) * s_rstd[r] * lng[c] + lnb[c];
    }
    __syncthreads();

    // GEMM 64x128 * 128x128, per-thread 4 rows x 8 cols, smem operands
    int rg = tid & 15;        // rows 4rg..4rg+3
    int c0 = (tid >> 4) * 8;  // broadcast-friendly: warp has 2 distinct c0
    u64 acc[4][4];
    #pragma unroll
    for (int i = 0; i < 4; i++)
        #pragma unroll
        for (int j = 0; j < 4; j++) acc[i][j] = 0ull;

    #pragma unroll 2
    for (int k = 0; k < 128; k++) {
        const double* Wd = (const double*)(Wsm + k * 128 + c0);
        u64 w0 = __double_as_longlong(Wd[0]);
        u64 w1 = __double_as_longlong(Wd[1]);
        u64 w2 = __double_as_longlong(Wd[2]);
        u64 w3 = __double_as_longlong(Wd[3]);
        #pragma unroll
        for (int i = 0; i < 4; i++) {
            u64 av = f2_dup(As[(4 * rg + i) * PJS + k]);
            acc[i][0] = f2_fma(av, w0, acc[i][0]);
            acc[i][1] = f2_fma(av, w1, acc[i][1]);
            acc[i][2] = f2_fma(av, w2, acc[i][2]);
            acc[i][3] = f2_fma(av, w3, acc[i][3]);
        }
    }
    const double* Bd = (const double*)(biasv + c0);
    u64 bb0 = __double_as_longlong(Bd[0]);
    u64 bb1 = __double_as_longlong(Bd[1]);
    u64 bb2 = __double_as_longlong(Bd[2]);
    u64 bb3 = __double_as_longlong(Bd[3]);
    u64 sc = f2_dup(oscale);
    int head = c0 >> 5, dh0 = c0 & 31;
    #pragma unroll
    for (int i = 0; i < 4; i++) {
        int qrow = s0 + 4 * rg + i;
        u64* dst = (u64*)(outp + ((((size_t)(b * HEADS + head) * NV + n) * S + qrow) * DH + dh0));
        dst[0] = f2_mul(f2_add(acc[i][0], bb0), sc);
        dst[1] = f2_mul(f2_add(acc[i][1], bb1), sc);
        dst[2] = f2_mul(f2_add(acc[i][2], bb2), sc);
        dst[3] = f2_mul(f2_add(acc[i][3], bb3), sc);
    }
}

// ==================================================================
// Kernel 2: per-(view,split) flash attention partials. 2 queries/thread.
// grid (18, 12, 8), 64 threads. 288 keys in 4x72 chunks, cp.async
// double-buffered. smem 36KB -> 5 blocks/SM.
// ==================================================================
__device__ __forceinline__ void attn_chunk(
    const float4* Ks, const float4* Vs,
    const u64 qu[2][16], u64 Ov[2][16],
    float& m0, float& m1, float& l0, float& l1)
{
    #pragma unroll 1
    for (int g = 0; g < CHK / 8; g++) {
        float sc0[8], sc1[8];
        #pragma unroll
        for (int j = 0; j < 8; j++) {
            const double2* Kr = (const double2*)&Ks[(g * 8 + j) * 8];
            u64 a00 = 0, a01 = 0, a10 = 0, a11 = 0;
            #pragma unroll
            for (int i = 0; i < 4; i++) {
                double2 d0 = Kr[2 * i];
                double2 d1 = Kr[2 * i + 1];
                u64 k0 = __double_as_longlong(d0.x), k1 = __double_as_longlong(d0.y);
                u64 k2 = __double_as_longlong(d1.x), k3 = __double_as_longlong(d1.y);
                a00 = f2_fma(qu[0][4 * i + 0], k0, a00);
                a01 = f2_fma(qu[0][4 * i + 1], k1, a01);
                a00 = f2_fma(qu[0][4 * i + 2], k2, a00);
                a01 = f2_fma(qu[0][4 * i + 3], k3, a01);
                a10 = f2_fma(qu[1][4 * i + 0], k0, a10);
                a11 = f2_fma(qu[1][4 * i + 1], k1, a11);
                a10 = f2_fma(qu[1][4 * i + 2], k2, a10);
                a11 = f2_fma(qu[1][4 * i + 3], k3, a11);
            }
            float lo, hi;
            f2_unpack(lo, hi, f2_add(a00, a01)); sc0[j] = lo + hi;
            f2_unpack(lo, hi, f2_add(a10, a11)); sc1[j] = lo + hi;
        }
        float gm0 = sc0[0], gm1 = sc1[0];
        #pragma unroll
        for (int j = 1; j < 8; j++) { gm0 = fmaxf(gm0, sc0[j]); gm1 = fmaxf(gm1, sc1[j]); }
        if (gm0 > m0) {
            float sf = __expf(m0 - gm0);   // m=-inf -> 0
            l0 *= sf;
            u64 s2 = f2_dup(sf);
            #pragma unroll
            for (int e = 0; e < 16; e++) Ov[0][e] = f2_mul(Ov[0][e], s2);
            m0 = gm0;
        }
        if (gm1 > m1) {
            float sf = __expf(m1 - gm1);
            l1 *= sf;
            u64 s2 = f2_dup(sf);
            #pragma unroll
            for (int e = 0; e < 16; e++) Ov[1][e] = f2_mul(Ov[1][e], s2);
            m1 = gm1;
        }
        #pragma unroll
        for (int j = 0; j < 8; j++) {
            float p0 = __expf(sc0[j] - m0); l0 += p0;
            float p1 = __expf(sc1[j] - m1); l1 += p1;
            u64 pp0 = f2_dup(p0);
            u64 pp1 = f2_dup(p1);
            const double2* Vr = (const double2*)&Vs[(g * 8 + j) * 8];
            #pragma unroll
            for (int i = 0; i < 4; i++) {
                double2 v0 = Vr[2 * i];
                double2 v1 = Vr[2 * i + 1];
                u64 x0 = __double_as_longlong(v0.x), x1 = __double_as_longlong(v0.y);
                u64 x2 = __double_as_longlong(v1.x), x3 = __double_as_longlong(v1.y);
                Ov[0][4 * i + 0] = f2_fma(pp0, x0, Ov[0][4 * i + 0]);
                Ov[0][4 * i + 1] = f2_fma(pp0, x1, Ov[0][4 * i + 1]);
                Ov[0][4 * i + 2] = f2_fma(pp0, x2, Ov[0][4 * i + 2]);
                Ov[0][4 * i + 3] = f2_fma(pp0, x3, Ov[0][4 * i + 3]);
                Ov[1][4 * i + 0] = f2_fma(pp1, x0, Ov[1][4 * i + 0]);
                Ov[1][4 * i + 1] = f2_fma(pp1, x1, Ov[1][4 * i + 1]);
                Ov[1][4 * i + 2] = f2_fma(pp1, x2, Ov[1][4 * i + 2]);
                Ov[1][4 * i + 3] = f2_fma(pp1, x3, Ov[1][4 * i + 3]);
            }
        }
    }
}

__global__ __launch_bounds__(64, 5) void attn_kernel(
    const float* __restrict__ qp, const float* __restrict__ kp,
    const float* __restrict__ vp, float* __restrict__ Opart,
    float* __restrict__ ml)
{
    __shared__ float4 Ksm[2][CHK * 8];
    __shared__ float4 Vsm[2][CHK * 8];
    int qt = blockIdx.x;
    int ns = blockIdx.y;                 // n*2 + split
    int bh = blockIdx.z;
    int n = ns >> 1, split = ns & 1;
    int tid = threadIdx.x;
    size_t view = (size_t)bh * NV + n;
    size_t view2 = view * NSPLIT + split;
    int base = split * KSPL;

    const float4* Kb = (const float4*)(kp + view * KCNT * DH);
    const float4* Vb = (const float4*)(vp + view * KCNT * DH);

    // issue a CHK-key (K,V) stage into buffer buf
    auto issue = [&](int st, int buf) {
        const float4* Kg = Kb + (size_t)(base + st * CHK) * 8;
        const float4* Vg = Vb + (size_t)(base + st * CHK) * 8;
        #pragma unroll
        for (int i = 0; i < CHK * 8 / 64; i++) {
            int f = i * 64 + tid;
            cpa16(s2u(&Ksm[buf][f]), Kg + f);
            cpa16(s2u(&Vsm[buf][f]), Vg + f);
        }
        asm volatile("cp.async.commit_group;");
    };

    issue(0, 0);
    issue(1, 1);

    u64 qu[2][16];
    #pragma unroll
    for (int s = 0; s < 2; s++) {
        const u64* qrow = (const u64*)(qp + (view * QCNT + qt * 128 + s * 64 + tid) * DH);
        #pragma unroll
        for (int e = 0; e < 16; e++) qu[s][e] = qrow[e];   // pre-scaled by SCALEF
    }
    u64 Ov[2][16];
    #pragma unroll
    for (int s = 0; s < 2; s++)
        #pragma unroll
        for (int e = 0; e < 16; e++) Ov[s][e] = 0ull;
    float m0 = -CUDART_INF_F, m1 = -CUDART_INF_F, l0 = 0.f, l1 = 0.f;

    asm volatile("cp.async.wait_group 1;");
    __syncthreads();
    attn_chunk(Ksm[0], Vsm[0], qu, Ov, m0, m1, l0, l1);
    __syncthreads();
    issue(2, 0);
    asm volatile("cp.async.wait_group 1;");
    __syncthreads();
    attn_chunk(Ksm[1], Vsm[1], qu, Ov, m0, m1, l0, l1);
    __syncthreads();
    issue(3, 1);
    asm volatile("cp.async.wait_group 1;");
    __syncthreads();
    attn_chunk(Ksm[0], Vsm[0], qu, Ov, m0, m1, l0, l1);
    __syncthreads();
    asm volatile("cp.async.wait_group 0;");
    __syncthreads();
    attn_chunk(Ksm[1], Vsm[1], qu, Ov, m0, m1, l0, l1);

    #pragma unroll
    for (int s = 0; s < 2; s++) {
        size_t orow = view2 * QCNT + qt * 128 + s * 64 + tid;
        u64* dst = (u64*)(Opart + orow * DH);
        #pragma unroll
        for (int e = 0; e < 16; e++) dst[e] = Ov[s][e];
        ml[orow * 2]     = s ? m1 : m0;
        ml[orow * 2 + 1] = s ? l1 : l0;
    }
}

// ==================================================================
// Kernel 3: fused combine(12) + out-proj + skip + preLN + MLP + postLN
//           + transposed store.  256 threads, 32-row tiles.
// Thread map: rg = tid&15 (rows), cg = tid>>4 (cols) -> W broadcast.
// ==================================================================
#define CTP 130
__global__ __launch_bounds__(256) void tail_kernel(
    const float* __restrict__ Opart, const float* __restrict__ ml,
    const float* __restrict__ skip,
    const float* __restrict__ Wpm, const float* __restrict__ bpv,
    const float* __restrict__ preg, const float* __restrict__ preb,
    const float* __restrict__ W1m, const float* __restrict__ b1v,
    const float* __restrict__ W2m, const float* __restrict__ b2v,
    const float* __restrict__ postg, const float* __restrict__ postb,
    float* __restrict__ outp)
{
    extern __shared__ float dynT[];
    float* As  = dynT;                       // 32*CTP
    float* Bs  = As + 32 * CTP;              // 32*CTP
    float* Wsm = Bs + 32 * CTP;              // 16384
    float* sW  = Wsm + 16384;                // 128*NPART
    __shared__ float sm[32], sr[32];
    int tid = threadIdx.x;
    int gr0 = blockIdx.x * 32;          // rows are b*2304+q
    int b = gr0 / QCNT, q0 = gr0 - b * QCNT;

    // ---- stage combine weights: one thread per (row, head) ----
    if (tid < 128) {
        int r = tid >> 2, head = tid & 3;
        int q = q0 + r;
        size_t bhx = (size_t)b * HEADS + head;
        size_t rowbase = (bhx * NPART) * QCNT + q;
        float mv[NPART], lv[NPART], M = -CUDART_INF_F;
        #pragma unroll
        for (int n2 = 0; n2 < NPART; n2++) {
            size_t row = rowbase + (size_t)n2 * QCNT;
            mv[n2] = ml[row * 2];
            lv[n2] = ml[row * 2 + 1];
            M = fmaxf(M, mv[n2]);
        }
        float L = 0.f;
        float w[NPART];
        #pragma unroll
        for (int n2 = 0; n2 < NPART; n2++) {
            w[n2] = __expf(mv[n2] - M);
            L += w[n2] * lv[n2];
        }
        float Linv = __fdividef(1.f, L);
        #pragma unroll
        for (int n2 = 0; n2 < NPART; n2++)
            sW[tid * NPART + n2] = w[n2] * Linv;
    }
    __syncthreads();

    // ---- combine 12 partials into As; stage Wp into Wsm ----
    for (int idx = tid; idx < 4096; idx += 256) {
        int r = idx >> 7, c = idx & 127;
        int q = q0 + r;
        int head = c >> 5, dh = c & 31;
        size_t bhx = (size_t)b * HEADS + head;
        const float* wv = &sW[(r * 4 + head) * NPART];
        size_t obase = ((bhx * NPART) * QCNT + q) * DH + dh;
        float o = 0.f;
        #pragma unroll
        for (int n2 = 0; n2 < NPART; n2++)
            o += wv[n2] * Opart[obase + (size_t)n2 * QCNT * DH];
        As[r * CTP + c] = o;
    }
    {
        const float4* g = (const float4*)Wpm;
        float4* d = (float4*)Wsm;
        for (int i = tid; i < 4096; i += 256) d[i] = g[i];
    }
    __syncthreads();

    int rg = tid & 15, c0 = (tid >> 4) * 8;   // rows 2rg,2rg+1; W broadcast
    // ---- GEMM1: z = A @ Wp ----
    {
        u64 acc[2][4];
        #pragma unroll
        for (int i = 0; i < 2; i++)
            #pragma unroll
            for (int j = 0; j < 4; j++) acc[i][j] = 0ull;
        #pragma unroll 2
        for (int k = 0; k < 128; k++) {
            const double* Wd = (const double*)(Wsm + k * 128 + c0);
            u64 w0 = __double_as_longlong(Wd[0]);
            u64 w1 = __double_as_longlong(Wd[1]);
            u64 w2 = __double_as_longlong(Wd[2]);
            u64 w3 = __double_as_longlong(Wd[3]);
            #pragma unroll
            for (int i = 0; i < 2; i++) {
                u64 av = f2_dup(As[(2 * rg + i) * CTP + k]);
                acc[i][0] = f2_fma(av, w0, acc[i][0]);
                acc[i][1] = f2_fma(av, w1, acc[i][1]);
                acc[i][2] = f2_fma(av, w2, acc[i][2]);
                acc[i][3] = f2_fma(av, w3, acc[i][3]);
            }
        }
        const double* bd = (const double*)(bpv + c0);
        #pragma unroll
        for (int i = 0; i < 2; i++) {
            u64* dst = (u64*)&Bs[(2 * rg + i) * CTP + c0];
            #pragma unroll
            for (int j = 0; j < 4; j++)
                dst[j] = f2_add(acc[i][j], __double_as_longlong(bd[j]));
        }
    }
    __syncthreads();
    // ---- + skip, and stage W1 half0 into Wsm ----
    for (int idx = tid; idx < 4096; idx += 256) {
        int c = idx >> 5, r = idx & 31;
        Bs[r * CTP + c] += skip[((size_t)(b * DIMC + c)) * QCNT + q0 + r];
    }
    for (int i = tid; i < 4096; i += 256) {
        int k = i >> 5, c4 = i & 31;
        ((float4*)Wsm)[k * 32 + c4] = ((const float4*)(W1m + k * 256))[c4];
    }
    __syncthreads();
    // ---- pre-LN: 8 threads per row ----
    {
        int r = tid >> 3, p = tid & 7;
        const float* row = &Bs[r * CTP];
        float s = 0.f, s2 = 0.f;
        #pragma unroll 4
        for (int ci = 0; ci < 16; ci++) { float x = row[p + 8 * ci]; s += x; s2 += x * x; }
        s  += __shfl_xor_sync(0xffffffffu, s, 1);
        s2 += __shfl_xor_sync(0xffffffffu, s2, 1);
        s  += __shfl_xor_sync(0xffffffffu, s, 2);
        s2 += __shfl_xor_sync(0xffffffffu, s2, 2);
        s  += __shfl_xor_sync(0xffffffffu, s, 4);
        s2 += __shfl_xor_sync(0xffffffffu, s2, 4);
        if (p == 0) {
            float mn = s * (1.f / 128.f);
            float vv = s2 * (1.f / 128.f) - mn * mn;
            sm[r] = mn; sr[r] = rsqrtf(vv + 1e-5f);
        }
    }
    __syncthreads();
    for (int idx = tid; idx < 4096; idx += 256) {
        int r = idx >> 7, c = idx & 127;
        Bs[r * CTP + c] = (Bs[r * CTP + c] - sm[r]) * sr[r] * preg[c] + preb[c];
    }
    __syncthreads();
    // ---- MLP: two column-halves of W1/W2, weights staged through Wsm ----
    u64 acc2[2][4];
    #pragma unroll
    for (int i = 0; i < 2; i++)
        #pragma unroll
        for (int j = 0; j < 4; j++) acc2[i][j] = 0ull;
    #pragma unroll 1
    for (int half = 0; half < 2; half++) {
        // (Wsm holds W1 half on loop entry)
        u64 h[2][4];
        #pragma unroll
        for (int i = 0; i < 2; i++)
            #pragma unroll
            for (int j = 0; j < 4; j++) h[i][j] = 0ull;
        #pragma unroll 2
        for (int k = 0; k < 128; k++) {
            const double* Wd = (const double*)(Wsm + k * 128 + c0);
            u64 w0 = __double_as_longlong(Wd[0]);
            u64 w1 = __double_as_longlong(Wd[1]);
            u64 w2 = __double_as_longlong(Wd[2]);
            u64 w3 = __double_as_longlong(Wd[3]);
            #pragma unroll
            for (int i = 0; i < 2; i++) {
                u64 av = f2_dup(Bs[(2 * rg + i) * CTP + k]);
                h[i][0] = f2_fma(av, w0, h[i][0]);
                h[i][1] = f2_fma(av, w1, h[i][1]);
                h[i][2] = f2_fma(av, w2, h[i][2]);
                h[i][3] = f2_fma(av, w3, h[i][3]);
            }
        }
        const double* b1d = (const double*)(b1v + half * 128 + c0);
        #pragma unroll
        for (int i = 0; i < 2; i++)
            #pragma unroll
            for (int j = 0; j < 4; j++) {
                float lo, hi;
                f2_unpack(lo, hi, f2_add(h[i][j], __double_as_longlong(b1d[j])));
                float g0 = 0.5f * lo * (1.f + erff(lo * 0.70710678118654752f));
                float g1 = 0.5f * hi * (1.f + erff(hi * 0.70710678118654752f));
                As[(2 * rg + i) * CTP + c0 + 2 * j]     = g0;
                As[(2 * rg + i) * CTP + c0 + 2 * j + 1] = g1;
            }
        __syncthreads();
        // stage W2 half (contiguous block of 16384 floats)
        {
            const float4* g = (const float4*)(W2m + half * 16384);
            float4* d = (float4*)Wsm;
            for (int i = tid; i < 4096; i += 256) d[i] = g[i];
        }
        __syncthreads();
        #pragma unroll 2
        for (int k = 0; k < 128; k++) {
            const double* Wd = (const double*)(Wsm + k * 128 + c0);
            u64 w0 = __double_as_longlong(Wd[0]);
            u64 w1 = __double_as_longlong(Wd[1]);
            u64 w2 = __double_as_longlong(Wd[2]);
            u64 w3 = __double_as_longlong(Wd[3]);
            #pragma unroll
            for (int i = 0; i < 2; i++) {
                u64 av = f2_dup(As[(2 * rg + i) * CTP + k]);
                acc2[i][0] = f2_fma(av, w0, acc2[i][0]);
                acc2[i][1] = f2_fma(av, w1, acc2[i][1]);
                acc2[i][2] = f2_fma(av, w2, acc2[i][2]);
                acc2[i][3] = f2_fma(av, w3, acc2[i][3]);
            }
        }
        __syncthreads();
        if (half == 0) {
            // stage W1 half1 for next iteration
            for (int i = tid; i < 4096; i += 256) {
                int k = i >> 5, c4 = i & 31;
                ((float4*)Wsm)[k * 32 + c4] = ((const float4*)(W1m + k * 256 + 128))[c4];
            }
            __syncthreads();
        }
    }
    {
        const double* b2d = (const double*)(b2v + c0);
        #pragma unroll
        for (int i = 0; i < 2; i++) {
            u64* dst = (u64*)&Bs[(2 * rg + i) * CTP + c0];
            #pragma unroll
            for (int j = 0; j < 4; j++)
                dst[j] = f2_add(dst[j], f2_add(acc2[i][j], __double_as_longlong(b2d[j])));
        }
    }
    __syncthreads();
    // ---- post-LN: 8 threads per row ----
    {
        int r = tid >> 3, p = tid & 7;
        const float* row = &Bs[r * CTP];
        float s = 0.f, s2 = 0.f;
        #pragma unroll 4
        for (int ci = 0; ci < 16; ci++) { float x = row[p + 8 * ci]; s += x; s2 += x * x; }
        s  += __shfl_xor_sync(0xffffffffu, s, 1);
        s2 += __shfl_xor_sync(0xffffffffu, s2, 1);
        s  += __shfl_xor_sync(0xffffffffu, s, 2);
        s2 += __shfl_xor_sync(0xffffffffu, s2, 2);
        s  += __shfl_xor_sync(0xffffffffu, s, 4);
        s2 += __shfl_xor_sync(0xffffffffu, s2, 4);
        if (p == 0) {
            float mn = s * (1.f / 128.f);
            float vv = s2 * (1.f / 128.f) - mn * mn;
            sm[r] = mn; sr[r] = rsqrtf(vv + 1e-5f);
        }
    }
    __syncthreads();
    // ---- write transposed output (B, d, H, W) ----
    for (int idx = tid; idx < 4096; idx += 256) {
        int c = idx >> 5, r = idx & 31;
        float z = (Bs[r * CTP + c] - sm[r]) * sr[r] * postg[c] + postb[c];
        outp[((size_t)(b * DIMC + c)) * QCNT + q0 + r] = z;
    }
}

// ==================================================================
extern "C" void kernel_launch(void* const* d_in, const int* in_sizes, int n_in,
                              void* d_out, int out_size)
{
    const float* q     = (const float*)d_in[0];
    const float* k     = (const float*)d_in[1];
    const float* v     = (const float*)d_in[2];
    const float* skip  = (const float*)d_in[3];
    const float* lnq_g = (const float*)d_in[4];
    const float* lnq_b = (const float*)d_in[5];
    const float* Wq    = (const float*)d_in[6];
    const float* bq    = (const float*)d_in[7];
    const float* lnk_g = (const float*)d_in[8];
    const float* lnk_b = (const float*)d_in[9];
    const float* Wk    = (const float*)d_in[10];
    const float* bk    = (const float*)d_in[11];
    const float* lnv_g = (const float*)d_in[12];
    const float* lnv_b = (const float*)d_in[13];
    const float* Wv    = (const float*)d_in[14];
    const float* bv    = (const float*)d_in[15];
    const float* Wp    = (const float*)d_in[16];
    const float* bp    = (const float*)d_in[17];
    const float* pre_g = (const float*)d_in[18];
    const float* pre_b = (const float*)d_in[19];
    const float* W1    = (const float*)d_in[20];
    const float* b1    = (const float*)d_in[21];
    const float* W2    = (const float*)d_in[22];
    const float* b2    = (const float*)d_in[23];
    const float* post_g= (const float*)d_in[24];
    const float* post_b= (const float*)d_in[25];
    float* outp = (float*)d_out;

    float *qp, *kpb, *vpb, *Opart, *mlb;
    cudaGetSymbolAddress((void**)&qp,   g_qp);
    cudaGetSymbolAddress((void**)&kpb,  g_kp);
    cudaGetSymbolAddress((void**)&vpb,  g_vp);
    cudaGetSymbolAddress((void**)&Opart,g_Opart);
    cudaGetSymbolAddress((void**)&mlb,  g_ml);

    const int PROJ_SMEM = (64 * PJS + 128 * 128) * sizeof(float);               // 98560
    const int TAIL_SMEM = (2 * 32 * CTP + 16384 + 128 * NPART) * sizeof(float); // 104960
    cudaFuncSetAttribute(proj_all_kernel,
                         cudaFuncAttributeMaxDynamicSharedMemorySize, PROJ_SMEM);
    cudaFuncSetAttribute(tail_kernel,
                         cudaFuncAttributeMaxDynamicSharedMemorySize, TAIL_SMEM);

    proj_all_kernel<<<648, 256, PROJ_SMEM>>>(q, k, v,
        lnq_g, lnq_b, Wq, bq, lnk_g, lnk_b, Wk, bk, lnv_g, lnv_b, Wv, bv,
        qp, kpb, vpb);

    dim3 ag(QCNT / 128, NPART, BH);
    attn_kernel<<<ag, 64>>>(qp, kpb, vpb, Opart, mlb);

    tail_kernel<<<(BB * QCNT) / 32, 256, TAIL_SMEM>>>(Opart, mlb, skip, Wp, bp, pre_g, pre_b,
                                           W1, b1, W2, b2, post_g, post_b, outp);
}